// round 4
// baseline (speedup 1.0000x reference)
#include <cuda_runtime.h>
#include <cuda_bf16.h>
#include <cstdint>

#define N_NODES 50000
#define N_EDGES 800000
#define D 128

// ---------------------------------------------------------------------------
// Device scratch (no allocation allowed in kernel_launch)
// ---------------------------------------------------------------------------
__device__ int    g_cin[N_NODES];       // # edges with src = n   (deg_in  - 1)
__device__ int    g_cnt[N_NODES];       // # edges with dst = n   (deg_out - 1)
__device__ int    g_rowptr[N_NODES + 1];
__device__ int    g_cursor[N_NODES];
__device__ int    g_col[N_EDGES];
__device__ float  g_xs[N_NODES * D];    // x * rsqrt(deg_in)
__device__ float  g_upd[N_NODES * D];   // aggregated update (written once)
__device__ float2 g_W2[D * (D / 2)];    // W packed by output-column pairs

// ---------------------------------------------------------------------------
// Packed f32x2 helpers (base Blackwell family ops — NOT 'a'-gated)
// ---------------------------------------------------------------------------
__device__ __forceinline__ unsigned long long pack2(float lo, float hi) {
    unsigned long long r;
    asm("mov.b64 %0, {%1, %2};" : "=l"(r) : "f"(lo), "f"(hi));
    return r;
}
__device__ __forceinline__ void fma2(unsigned long long& d,
                                     unsigned long long a,
                                     unsigned long long b) {
    asm("fma.rn.f32x2 %0, %1, %2, %0;" : "+l"(d) : "l"(a), "l"(b));
}
__device__ __forceinline__ void unpack2(unsigned long long v, float& lo, float& hi) {
    asm("mov.b64 {%0, %1}, %2;" : "=f"(lo), "=f"(hi) : "l"(v));
}

// ---------------------------------------------------------------------------
// Kernel 1: zero count arrays
// ---------------------------------------------------------------------------
__global__ void init_kernel() {
    int i = blockIdx.x * blockDim.x + threadIdx.x;
    if (i < N_NODES) { g_cin[i] = 0; g_cnt[i] = 0; }
}

// ---------------------------------------------------------------------------
// Kernel 2: degree counts
// ---------------------------------------------------------------------------
__global__ void degree_kernel(const int2* __restrict__ edges) {
    int i = blockIdx.x * blockDim.x + threadIdx.x;
    if (i < N_EDGES) {
        int2 e = edges[i];
        atomicAdd(&g_cin[e.x], 1);
        atomicAdd(&g_cnt[e.y], 1);
    }
}

// ---------------------------------------------------------------------------
// Kernel 3a: xs = x * rsqrt(deg_in)   (deg_in = cin+1; eps ~1e-10 negligible)
// ---------------------------------------------------------------------------
__global__ void scale_kernel(const float* __restrict__ x) {
    int i = blockIdx.x * blockDim.x + threadIdx.x;   // float4 index
    if (i < N_NODES * (D / 4)) {
        int row = i >> 5;
        float s = rsqrtf((float)(g_cin[row] + 1));
        float4 v = reinterpret_cast<const float4*>(x)[i];
        v.x *= s; v.y *= s; v.z *= s; v.w *= s;
        reinterpret_cast<float4*>(g_xs)[i] = v;
    }
}

// ---------------------------------------------------------------------------
// Kernel 3b: pack W into column pairs: W2[k*64 + j] = {W[2j][k], W[2j+1][k]}
// ---------------------------------------------------------------------------
__global__ void wpack_kernel(const float* __restrict__ Wm) {
    int i = blockIdx.x * blockDim.x + threadIdx.x;
    if (i < D * (D / 2)) {
        int k = i >> 6;        // 0..127
        int j = i & 63;        // colpair 0..63
        g_W2[i] = make_float2(Wm[(2 * j) * D + k], Wm[(2 * j + 1) * D + k]);
    }
}

// ---------------------------------------------------------------------------
// Kernel 4: exclusive scan of g_cnt -> row_ptr, cursor  (single CTA)
// ---------------------------------------------------------------------------
#define SCAN_T 1024
#define SCAN_CHUNK 49   // 1024*49 = 50176 >= 50000
__global__ __launch_bounds__(SCAN_T) void scan_kernel() {
    __shared__ int part[SCAN_T];
    int t = threadIdx.x;
    int base = t * SCAN_CHUNK;
    int s = 0;
    for (int i = 0; i < SCAN_CHUNK; i++) {
        int idx = base + i;
        if (idx < N_NODES) s += g_cnt[idx];
    }
    part[t] = s;
    __syncthreads();
    for (int off = 1; off < SCAN_T; off <<= 1) {
        int v = (t >= off) ? part[t - off] : 0;
        __syncthreads();
        part[t] += v;
        __syncthreads();
    }
    int run = part[t] - s;   // exclusive prefix for this chunk
    for (int i = 0; i < SCAN_CHUNK; i++) {
        int idx = base + i;
        if (idx < N_NODES) {
            g_rowptr[idx] = run;
            g_cursor[idx] = run;
            run += g_cnt[idx];
        }
    }
    if (t == SCAN_T - 1) g_rowptr[N_NODES] = run;
}

// ---------------------------------------------------------------------------
// Kernel 5: fill CSR column array (order within a node arbitrary)
// ---------------------------------------------------------------------------
__global__ void fill_kernel(const int2* __restrict__ edges) {
    int i = blockIdx.x * blockDim.x + threadIdx.x;
    if (i < N_EDGES) {
        int2 e = edges[i];
        int pos = atomicAdd(&g_cursor[e.y], 1);
        g_col[pos] = e.x;
    }
}

// ---------------------------------------------------------------------------
// Kernel 6: gather-accumulate. One warp per destination node.
// update[v] = rsqrt(deg_out[v]) * ( xs[v] + sum_{(u,v)} xs[u] )
// Each row written exactly once (no atomics).
// ---------------------------------------------------------------------------
__global__ __launch_bounds__(256) void gather_kernel() {
    int v    = (blockIdx.x * blockDim.x + threadIdx.x) >> 5;
    int lane = threadIdx.x & 31;
    if (v >= N_NODES) return;

    const float4* xs4 = reinterpret_cast<const float4*>(g_xs);
    float4 acc = xs4[v * 32 + lane];    // self loop (already deg_in-scaled)

    int start = g_rowptr[v];
    int end   = g_rowptr[v + 1];
    for (int base = start; base < end; base += 32) {
        int j = base + lane;
        int u = (j < end) ? g_col[j] : 0;
        int cnt = min(32, end - base);
        int k = 0;
        // 2-way unrolled broadcast loop for a little more MLP
        for (; k + 2 <= cnt; k += 2) {
            int u0 = __shfl_sync(0xffffffffu, u, k);
            int u1 = __shfl_sync(0xffffffffu, u, k + 1);
            float4 t0 = xs4[u0 * 32 + lane];
            float4 t1 = xs4[u1 * 32 + lane];
            acc.x += t0.x; acc.y += t0.y; acc.z += t0.z; acc.w += t0.w;
            acc.x += t1.x; acc.y += t1.y; acc.z += t1.z; acc.w += t1.w;
        }
        if (k < cnt) {
            int u0 = __shfl_sync(0xffffffffu, u, k);
            float4 t0 = xs4[u0 * 32 + lane];
            acc.x += t0.x; acc.y += t0.y; acc.z += t0.z; acc.w += t0.w;
        }
    }
    float s = rsqrtf((float)(g_cnt[v] + 1));
    acc.x *= s; acc.y *= s; acc.z *= s; acc.w *= s;
    reinterpret_cast<float4*>(g_upd)[v * 32 + lane] = acc;
}

// ---------------------------------------------------------------------------
// Kernel 7: out = relu(U @ W^T + b) using packed fma.rn.f32x2 (FFMA2).
// Block = 256 threads, 64-row x 128-col tile.
// Thread (warp w, lane l): rows w*8..w*8+7, col pairs j = l and l+32
//   -> columns {2j, 2j+1}. Per 4-k chunk: 8 LDS.128 (U broadcast) +
//   8 LDS.64 (W2) -> 64 FFMA2 (128 FMA lanes) : FMA-pipe bound.
// ---------------------------------------------------------------------------
#define GEMM_ROWS 64
#define GEMM_SMEM (GEMM_ROWS * D * 4 + D * (D / 2) * 8)   // 32KB + 64KB

__global__ __launch_bounds__(256) void gemm_kernel(
    const float* __restrict__ b, float* __restrict__ out) {
    extern __shared__ float smem[];
    float*  Us  = smem;                      // [64][128]
    float2* Ws2 = reinterpret_cast<float2*>(smem + GEMM_ROWS * D);  // [128][64]

    int tid  = threadIdx.x;
    int lane = tid & 31;
    int warp = tid >> 5;
    int row0 = blockIdx.x * GEMM_ROWS;

    // Stage W2 (pre-packed): 4096 float4 chunks
    {
        const float4* src = reinterpret_cast<const float4*>(g_W2);
        float4* dst = reinterpret_cast<float4*>(Ws2);
        for (int t = tid; t < D * (D / 2) / 2; t += 256) dst[t] = src[t];
    }
    // Stage U tile (zero-fill past N)
    {
        const float4* src = reinterpret_cast<const float4*>(g_upd);
        float4* dst = reinterpret_cast<float4*>(Us);
        for (int t = tid; t < GEMM_ROWS * (D / 4); t += 256) {
            int r = t >> 5;
            int row = row0 + r;
            dst[t] = (row < N_NODES) ? src[row * 32 + (t & 31)]
                                     : make_float4(0.f, 0.f, 0.f, 0.f);
        }
    }
    __syncthreads();

    unsigned long long acc[8][2];
#pragma unroll
    for (int i = 0; i < 8; i++) { acc[i][0] = 0ull; acc[i][1] = 0ull; }

    int r0 = warp * 8;
    int j0 = lane, j1 = lane + 32;

#pragma unroll
    for (int k = 0; k < D; k += 4) {
        unsigned long long wv[2][4];
#pragma unroll
        for (int kk = 0; kk < 4; kk++) {
            wv[0][kk] = *reinterpret_cast<const unsigned long long*>(&Ws2[(k + kk) * 64 + j0]);
            wv[1][kk] = *reinterpret_cast<const unsigned long long*>(&Ws2[(k + kk) * 64 + j1]);
        }
#pragma unroll
        for (int i = 0; i < 8; i++) {
            float4 u = *reinterpret_cast<const float4*>(&Us[(r0 + i) * D + k]);
            unsigned long long u0 = pack2(u.x, u.x);
            unsigned long long u1 = pack2(u.y, u.y);
            unsigned long long u2 = pack2(u.z, u.z);
            unsigned long long u3 = pack2(u.w, u.w);
            fma2(acc[i][0], u0, wv[0][0]);  fma2(acc[i][1], u0, wv[1][0]);
            fma2(acc[i][0], u1, wv[0][1]);  fma2(acc[i][1], u1, wv[1][1]);
            fma2(acc[i][0], u2, wv[0][2]);  fma2(acc[i][1], u2, wv[1][2]);
            fma2(acc[i][0], u3, wv[0][3]);  fma2(acc[i][1], u3, wv[1][3]);
        }
    }

    // Epilogue: bias + relu, 8B coalesced stores (lane l -> cols 2l, 2l+1)
    float2 b0 = *reinterpret_cast<const float2*>(&b[2 * j0]);
    float2 b1 = *reinterpret_cast<const float2*>(&b[2 * j1]);
#pragma unroll
    for (int i = 0; i < 8; i++) {
        int row = row0 + r0 + i;
        if (row < N_NODES) {
            float lo, hi;
            unpack2(acc[i][0], lo, hi);
            float2 v0 = make_float2(fmaxf(lo + b0.x, 0.f), fmaxf(hi + b0.y, 0.f));
            unpack2(acc[i][1], lo, hi);
            float2 v1 = make_float2(fmaxf(lo + b1.x, 0.f), fmaxf(hi + b1.y, 0.f));
            *reinterpret_cast<float2*>(&out[(size_t)row * D + 2 * j0]) = v0;
            *reinterpret_cast<float2*>(&out[(size_t)row * D + 2 * j1]) = v1;
        }
    }
}

// ---------------------------------------------------------------------------
// Launch. Inputs: edge_list [800000,2] i32, x [50000,128] f32,
//                 W [128,128] f32, b [128] f32. Output f32 [50000,128].
// ---------------------------------------------------------------------------
extern "C" void kernel_launch(void* const* d_in, const int* in_sizes, int n_in,
                              void* d_out, int out_size) {
    const int2*  edges = (const int2*) d_in[0];
    const float* x     = (const float*)d_in[1];
    const float* Wm    = (const float*)d_in[2];
    const float* b     = (const float*)d_in[3];
    float* out = (float*)d_out;

    static bool attr_done = false;
    if (!attr_done) {
        cudaFuncSetAttribute(gemm_kernel,
                             cudaFuncAttributeMaxDynamicSharedMemorySize, GEMM_SMEM);
        attr_done = true;
    }

    init_kernel<<<(N_NODES + 255) / 256, 256>>>();
    degree_kernel<<<(N_EDGES + 255) / 256, 256>>>(edges);
    scale_kernel<<<(N_NODES * (D / 4) + 255) / 256, 256>>>(x);
    wpack_kernel<<<(D * (D / 2) + 255) / 256, 256>>>(Wm);
    scan_kernel<<<1, SCAN_T>>>();
    fill_kernel<<<(N_EDGES + 255) / 256, 256>>>(edges);
    gather_kernel<<<(N_NODES + 7) / 8, 256>>>();
    gemm_kernel<<<(N_NODES + GEMM_ROWS - 1) / GEMM_ROWS, 256, GEMM_SMEM>>>(b, out);
}

// round 6
// speedup vs baseline: 1.3176x; 1.3176x over previous
#include <cuda_runtime.h>
#include <cuda_fp16.h>
#include <cstdint>

#define N_NODES 50000
#define N_EDGES 800000
#define D 128

// ---------------------------------------------------------------------------
// Device scratch (no allocation allowed in kernel_launch)
// ---------------------------------------------------------------------------
__device__ int     g_cin[N_NODES];        // deg_in  - 1 (edge src counts)
__device__ int     g_cnt[N_NODES];        // deg_out - 1 (edge dst counts)
__device__ float   g_sout[N_NODES];       // rsqrt(deg_out)
__device__ __half  g_xsh[N_NODES * D];    // fp16( x * rsqrt(deg_in) )
__device__ float   g_upd[N_NODES * D];    // fp32 accumulator (self-loop preloaded)
__device__ float2  g_W2[D * (D / 2)];     // W2[k*64+j] = {W[2j][k], W[2j+1][k]}

// ---------------------------------------------------------------------------
// Packed f32x2 helpers (base-family Blackwell ops; compile confirmed R4)
// ---------------------------------------------------------------------------
__device__ __forceinline__ unsigned long long pack2dup(float v) {
    unsigned long long r;
    asm("mov.b64 %0, {%1, %1};" : "=l"(r) : "f"(v));
    return r;
}
__device__ __forceinline__ void fma2(unsigned long long& d,
                                     unsigned long long a,
                                     unsigned long long b) {
    asm("fma.rn.f32x2 %0, %1, %2, %0;" : "+l"(d) : "l"(a), "l"(b));
}
__device__ __forceinline__ void unpack2(unsigned long long v, float& lo, float& hi) {
    asm("mov.b64 {%0, %1}, %2;" : "=f"(lo), "=f"(hi) : "l"(v));
}

#define ZB ((N_NODES + 255) / 256)                  // 196
#define DB ((N_EDGES + 255) / 256)                  // 3125
#define WB ((D * (D / 2) + 255) / 256)              // 32

// ---------------------------------------------------------------------------
// Kernel 1: zero degree counters
// ---------------------------------------------------------------------------
__global__ void zero_kernel() {
    int i = blockIdx.x * blockDim.x + threadIdx.x;
    if (i < N_NODES) { g_cin[i] = 0; g_cnt[i] = 0; }
}

// ---------------------------------------------------------------------------
// Kernel 2: degree counts + W pack (disjoint block ranges)
// ---------------------------------------------------------------------------
__global__ __launch_bounds__(256) void prep2_kernel(const int2* __restrict__ edges,
                                                    const float* __restrict__ Wm) {
    int bid = blockIdx.x;
    if (bid < DB) {
        int i = bid * 256 + threadIdx.x;
        if (i < N_EDGES) {
            int2 e = edges[i];
            atomicAdd(&g_cin[e.x], 1);
            atomicAdd(&g_cnt[e.y], 1);
        }
    } else {
        int i = (bid - DB) * 256 + threadIdx.x;
        if (i < D * (D / 2)) {
            int k = i >> 6;        // 0..127
            int j = i & 63;        // col pair 0..63
            g_W2[i] = make_float2(Wm[(2 * j) * D + k], Wm[(2 * j + 1) * D + k]);
        }
    }
}

// ---------------------------------------------------------------------------
// Kernel 3: scale + self-loop preload.
//   g_upd = x * rsqrt(deg_in)  (fp32 self-loop term, accumulator base)
//   g_xsh = fp16 of the same   (message payload)
//   g_sout = rsqrt(deg_out)
// ---------------------------------------------------------------------------
__global__ __launch_bounds__(256) void scale_kernel(const float* __restrict__ x) {
    int i = blockIdx.x * blockDim.x + threadIdx.x;   // float4 index
    if (i < N_NODES * (D / 4)) {
        int row = i >> 5;
        float s = rsqrtf((float)(g_cin[row] + 1));
        float4 v = reinterpret_cast<const float4*>(x)[i];
        v.x *= s; v.y *= s; v.z *= s; v.w *= s;
        reinterpret_cast<float4*>(g_upd)[i] = v;          // self-loop term
        __half2 h0 = __floats2half2_rn(v.x, v.y);
        __half2 h1 = __floats2half2_rn(v.z, v.w);
        *reinterpret_cast<__half2*>(&g_xsh[(size_t)i * 4])     = h0;
        *reinterpret_cast<__half2*>(&g_xsh[(size_t)i * 4 + 2]) = h1;
        if ((i & 31) == 0) g_sout[row] = rsqrtf((float)(g_cnt[row] + 1));
    }
}

// ---------------------------------------------------------------------------
// Kernel 4: edge scatter. One warp per edge. Lane l covers features [4l,4l+4).
//   g_upd[v] += fp32(fp16row(xs[u]))   via red.global.add.v4.f32
// ---------------------------------------------------------------------------
__global__ __launch_bounds__(256) void scatter_kernel(const int2* __restrict__ edges) {
    int gw   = (blockIdx.x * blockDim.x + threadIdx.x) >> 5;
    int lane = threadIdx.x & 31;
    if (gw >= N_EDGES) return;

    int2 e = edges[gw];                 // broadcast 8B load
    int u = e.x, v = e.y;

    uint2 raw = *reinterpret_cast<const uint2*>(&g_xsh[(size_t)u * D + lane * 4]);
    __half2 h0 = *reinterpret_cast<__half2*>(&raw.x);
    __half2 h1 = *reinterpret_cast<__half2*>(&raw.y);
    float2 f0 = __half22float2(h0);
    float2 f1 = __half22float2(h1);

    float* dst = &g_upd[(size_t)v * D + lane * 4];
    asm volatile("red.global.add.v4.f32 [%0], {%1,%2,%3,%4};"
                 :: "l"(dst), "f"(f0.x), "f"(f0.y), "f"(f1.x), "f"(f1.y)
                 : "memory");
}

// ---------------------------------------------------------------------------
// Kernel 5: out = relu((sout*U) @ W^T + b) with packed FFMA2.
// 256 threads, 64-row tile. smem = U tile only (32KB static) -> 3 CTAs/SM.
// Thread (warp w, lane l): rows w*8..w*8+7, col pairs j0=l, j1=l+32
//   (cols 2j, 2j+1). W2 read via coalesced __ldg (L1-resident 64KB).
// ---------------------------------------------------------------------------
#define GEMM_ROWS 64
__global__ __launch_bounds__(256, 3) void gemm_kernel(
    const float* __restrict__ b, float* __restrict__ out) {
    __shared__ float Us[GEMM_ROWS * D];   // 32KB

    int tid  = threadIdx.x;
    int lane = tid & 31;
    int warp = tid >> 5;
    int row0 = blockIdx.x * GEMM_ROWS;

    // Stage U tile scaled by sout (rows beyond N zero-filled)
    {
        const float4* src = reinterpret_cast<const float4*>(g_upd);
        float4* dst = reinterpret_cast<float4*>(Us);
        for (int t = tid; t < GEMM_ROWS * (D / 4); t += 256) {
            int r = t >> 5;
            int row = row0 + r;
            float4 v = make_float4(0.f, 0.f, 0.f, 0.f);
            if (row < N_NODES) {
                float s = g_sout[row];
                v = src[(size_t)row * 32 + (t & 31)];
                v.x *= s; v.y *= s; v.z *= s; v.w *= s;
            }
            dst[t] = v;
        }
    }
    __syncthreads();

    unsigned long long acc[8][2];
#pragma unroll
    for (int i = 0; i < 8; i++) { acc[i][0] = 0ull; acc[i][1] = 0ull; }

    int r0 = warp * 8;
    int j0 = lane, j1 = lane + 32;
    const float2* W2 = g_W2;

#pragma unroll
    for (int k = 0; k < D; k += 4) {
        unsigned long long wv0[4], wv1[4];
#pragma unroll
        for (int kk = 0; kk < 4; kk++) {
            float2 a = __ldg(&W2[(k + kk) * 64 + j0]);
            float2 c = __ldg(&W2[(k + kk) * 64 + j1]);
            asm("mov.b64 %0, {%1, %2};" : "=l"(wv0[kk]) : "f"(a.x), "f"(a.y));
            asm("mov.b64 %0, {%1, %2};" : "=l"(wv1[kk]) : "f"(c.x), "f"(c.y));
        }
#pragma unroll
        for (int i = 0; i < 8; i++) {
            float4 u = *reinterpret_cast<const float4*>(&Us[(r0 + i) * D + k]);
            unsigned long long u0 = pack2dup(u.x);
            unsigned long long u1 = pack2dup(u.y);
            unsigned long long u2 = pack2dup(u.z);
            unsigned long long u3 = pack2dup(u.w);
            fma2(acc[i][0], u0, wv0[0]);  fma2(acc[i][1], u0, wv1[0]);
            fma2(acc[i][0], u1, wv0[1]);  fma2(acc[i][1], u1, wv1[1]);
            fma2(acc[i][0], u2, wv0[2]);  fma2(acc[i][1], u2, wv1[2]);
            fma2(acc[i][0], u3, wv0[3]);  fma2(acc[i][1], u3, wv1[3]);
        }
    }

    // Epilogue: bias + relu, 8B coalesced stores (cols 2j, 2j+1)
    float2 b0 = *reinterpret_cast<const float2*>(&b[2 * j0]);
    float2 b1 = *reinterpret_cast<const float2*>(&b[2 * j1]);
#pragma unroll
    for (int i = 0; i < 8; i++) {
        int row = row0 + r0 + i;
        if (row < N_NODES) {
            float lo, hi;
            unpack2(acc[i][0], lo, hi);
            float2 v0 = make_float2(fmaxf(lo + b0.x, 0.f), fmaxf(hi + b0.y, 0.f));
            unpack2(acc[i][1], lo, hi);
            float2 v1 = make_float2(fmaxf(lo + b1.x, 0.f), fmaxf(hi + b1.y, 0.f));
            *reinterpret_cast<float2*>(&out[(size_t)row * D + 2 * j0]) = v0;
            *reinterpret_cast<float2*>(&out[(size_t)row * D + 2 * j1]) = v1;
        }
    }
}

// ---------------------------------------------------------------------------
// Launch. Inputs: edge_list [800000,2] i32, x [50000,128] f32,
//                 W [128,128] f32, b [128] f32. Output f32 [50000,128].
// ---------------------------------------------------------------------------
extern "C" void kernel_launch(void* const* d_in, const int* in_sizes, int n_in,
                              void* d_out, int out_size) {
    const int2*  edges = (const int2*) d_in[0];
    const float* x     = (const float*)d_in[1];
    const float* Wm    = (const float*)d_in[2];
    const float* b     = (const float*)d_in[3];
    float* out = (float*)d_out;

    zero_kernel<<<ZB, 256>>>();
    prep2_kernel<<<DB + WB, 256>>>(edges, Wm);
    scale_kernel<<<(N_NODES * (D / 4) + 255) / 256, 256>>>(x);
    {
        int blocks = (N_EDGES + 7) / 8;            // 8 warps per 256-thread block
        scatter_kernel<<<blocks, 256>>>(edges);
    }
    gemm_kernel<<<(N_NODES + GEMM_ROWS - 1) / GEMM_ROWS, 256>>>(b, out);
}